// round 2
// baseline (speedup 1.0000x reference)
#include <cuda_runtime.h>

#define BB   8
#define SEQ  1024
#define DMOD 1024
#define NH   16
#define DK   64
#define NBH  128   // BB*NH

// Scratch (device globals — allocation-free per harness rules)
__device__ float g_Q[(size_t)NBH * SEQ * DK];           // [bh][s][d]  33.5MB
__device__ float g_K[(size_t)NBH * SEQ * DK];
__device__ float g_V[(size_t)NBH * SEQ * DK];
__device__ float g_E2[(size_t)NBH * SEQ * SEQ];         // [bh][q][k]  512MB

// ---------------------------------------------------------------------------
// Projection GEMM: out[bh][s][d] = (X @ W + b) with head-split layout.
// 64x64 tile, BK=16, 256 threads, 4x4 micro-tile.
// ---------------------------------------------------------------------------
__global__ __launch_bounds__(256, 4)
void proj_kernel(const float* __restrict__ X, const float* __restrict__ W,
                 const float* __restrict__ bias, int which)
{
    __shared__ float Ast[16][64];   // [k][m]
    __shared__ float Bs[16][64];    // [k][n]
    const int t  = threadIdx.x;
    const int tx = t & 15, ty = t >> 4;
    const int n0 = blockIdx.x * 64;      // head = blockIdx.x
    const int m0 = blockIdx.y * 64;

    const int am = t >> 2,  af = (t & 3) << 2;   // A loader
    const int bk = t >> 4,  bc = (t & 15) << 2;  // B loader

    float acc[4][4] = {};
    for (int k0 = 0; k0 < DMOD; k0 += 16) {
        float4 av = *(const float4*)&X[(size_t)(m0 + am) * DMOD + k0 + af];
        float4 bv = *(const float4*)&W[(size_t)(k0 + bk) * DMOD + n0 + bc];
        __syncthreads();
        Ast[af + 0][am] = av.x; Ast[af + 1][am] = av.y;
        Ast[af + 2][am] = av.z; Ast[af + 3][am] = av.w;
        *(float4*)&Bs[bk][bc] = bv;
        __syncthreads();
        #pragma unroll
        for (int k = 0; k < 16; k++) {
            float4 a = *(const float4*)&Ast[k][ty << 2];
            float4 b = *(const float4*)&Bs[k][tx << 2];
            float as[4] = {a.x, a.y, a.z, a.w};
            float bs[4] = {b.x, b.y, b.z, b.w};
            #pragma unroll
            for (int i = 0; i < 4; i++)
                #pragma unroll
                for (int j = 0; j < 4; j++)
                    acc[i][j] += as[i] * bs[j];
        }
    }

    float* out = (which == 0) ? g_Q : (which == 1) ? g_K : g_V;
    const int b = m0 >> 10;            // 64 | 1024, tile within one batch
    const int h = blockIdx.x;
    float4 bb = *(const float4*)&bias[n0 + (tx << 2)];
    #pragma unroll
    for (int i = 0; i < 4; i++) {
        int m = m0 + (ty << 2) + i;
        int s = m & (SEQ - 1);
        float4 o = make_float4(acc[i][0] + bb.x, acc[i][1] + bb.y,
                               acc[i][2] + bb.z, acc[i][3] + bb.w);
        *(float4*)&out[(((size_t)(b * NH + h)) * SEQ + s) * DK + (tx << 2)] = o;
    }
}

// ---------------------------------------------------------------------------
// E2[bh][q][k] = sum_d Q[bh][q][d] * rel[q][k][d]
// Per block: fixed q, 64-wide k tile, all 128 bh. rel read exactly once.
// ---------------------------------------------------------------------------
__global__ __launch_bounds__(256, 3)
void e2_kernel(const float* __restrict__ rel)
{
    __shared__ float Qst[64 * 128];
    __shared__ float Rst[64 * 64];
    const int t  = threadIdx.x;
    const int tx = t & 15, ty = t >> 4;
    const int q  = blockIdx.y;
    const int k0 = blockIdx.x * 64;

    #pragma unroll
    for (int p = 0; p < 32; p++) {                 // 8192 scalars, coalesced
        int idx = p * 256 + t;
        int bh = idx >> 6, d = idx & 63;
        Qst[(d << 7) + ((((bh >> 2) ^ (d & 15)) << 2) | (bh & 3))] =
            g_Q[((size_t)bh * SEQ + q) * DK + d];
    }
    const float* rbase = rel + ((size_t)q * SEQ + k0) * DK;   // contiguous 4096
    #pragma unroll
    for (int p = 0; p < 16; p++) {
        int idx = p * 256 + t;
        int kk = idx >> 6, d = idx & 63;
        Rst[(d << 6) + ((((kk >> 2) ^ (d & 15)) << 2) | (kk & 3))] = rbase[idx];
    }
    __syncthreads();

    float acc[8][4] = {};
    #pragma unroll 16
    for (int d = 0; d < 64; d++) {
        int sw = d & 15;
        float4 a0 = *(const float4*)&Qst[(d << 7) + ((ty ^ sw) << 2)];
        float4 a1 = *(const float4*)&Qst[(d << 7) + (((16 + ty) ^ sw) << 2)];
        float4 bq = *(const float4*)&Rst[(d << 6) + ((tx ^ sw) << 2)];
        float as[8] = {a0.x, a0.y, a0.z, a0.w, a1.x, a1.y, a1.z, a1.w};
        float bs[4] = {bq.x, bq.y, bq.z, bq.w};
        #pragma unroll
        for (int i = 0; i < 8; i++)
            #pragma unroll
            for (int j = 0; j < 4; j++)
                acc[i][j] += as[i] * bs[j];
    }

    #pragma unroll
    for (int i = 0; i < 8; i++) {
        int bh = (i < 4) ? (ty << 2) + i : 64 + (ty << 2) + (i - 4);
        size_t o = ((size_t)bh * SEQ + q) * SEQ + k0 + (tx << 2);
        *(float4*)&g_E2[o] = make_float4(acc[i][0], acc[i][1], acc[i][2], acc[i][3]);
    }
}

// ---------------------------------------------------------------------------
// Fused attention: per block (bh, 64-row q tile), flash-style over 64-wide
// k tiles.  scores = QK/8 + E2, masked_fill(-1e8), online softmax, P@V.
// mask is int32 (jax bool promoted by harness): nonzero = masked out.
// ---------------------------------------------------------------------------
#define ATTN_SMEM_FLOATS (64 * 64 * 3 + 64 * 68)
#define ATTN_SMEM_BYTES  (ATTN_SMEM_FLOATS * 4)

__global__ __launch_bounds__(256, 2)
void attn_kernel(const int* __restrict__ mask, float* __restrict__ out)
{
    extern __shared__ float sm[];
    float* Qst = sm;                 // [d][q] swizzled, 4096
    float* Kst = sm + 4096;         // [d][k] swizzled, 4096
    float* Vs  = sm + 8192;         // [k][d] natural,  4096
    float* Ssm = sm + 12288;        // [q][k] pad 68,   4352

    const int t  = threadIdx.x;
    const int tx = t & 15, ty = t >> 4;
    const int q0 = blockIdx.x * 64;
    const int bh = blockIdx.y;
    const int b  = bh >> 4, h = bh & 15;

    const float* qg = g_Q + ((size_t)bh * SEQ + q0) * DK;     // contiguous 4096
    #pragma unroll
    for (int p = 0; p < 16; p++) {
        int idx = p * 256 + t;
        int c = idx >> 6, d = idx & 63;
        Qst[(d << 6) + ((((c >> 2) ^ (d & 15)) << 2) | (c & 3))] = qg[idx];
    }

    float m_[4], l_[4], o_[4][4];
    #pragma unroll
    for (int i = 0; i < 4; i++) {
        m_[i] = -1e30f; l_[i] = 0.f;
        #pragma unroll
        for (int j = 0; j < 4; j++) o_[i][j] = 0.f;
    }

    const float* kg  = g_K + (size_t)bh * SEQ * DK;
    const float* vg  = g_V + (size_t)bh * SEQ * DK;
    const float* e2g = g_E2 + ((size_t)bh * SEQ + q0) * SEQ;
    const int*   mg  = mask + ((size_t)b * SEQ + q0) * SEQ;

    for (int kt = 0; kt < SEQ; kt += 64) {
        __syncthreads();                              // protect prev PV reads
        const float* kgt = kg + (size_t)kt * DK;
        #pragma unroll
        for (int p = 0; p < 16; p++) {
            int idx = p * 256 + t;
            int c = idx >> 6, d = idx & 63;
            Kst[(d << 6) + ((((c >> 2) ^ (d & 15)) << 2) | (c & 3))] = kgt[idx];
        }
        const float* vgt = vg + (size_t)kt * DK;
        #pragma unroll
        for (int p = 0; p < 4; p++) {
            int idx = (p * 256 + t) << 2;
            *(float4*)&Vs[idx] = *(const float4*)&vgt[idx];
        }
        __syncthreads();

        // prefetch E2 + mask rows (overlaps with QK compute)
        float4 e2v[4];
        int4   mk[4];
        #pragma unroll
        for (int i = 0; i < 4; i++) {
            int r = (ty << 2) + i;
            e2v[i] = *(const float4*)&e2g[(size_t)r * SEQ + kt + (tx << 2)];
            mk[i]  = *(const int4*)&mg[(size_t)r * SEQ + kt + (tx << 2)];
        }

        float s_[4][4] = {};
        #pragma unroll 16
        for (int d = 0; d < 64; d++) {
            int sw = d & 15;
            float4 qv = *(const float4*)&Qst[(d << 6) + ((ty ^ sw) << 2)];
            float4 kv = *(const float4*)&Kst[(d << 6) + ((tx ^ sw) << 2)];
            float qa[4] = {qv.x, qv.y, qv.z, qv.w};
            float ka[4] = {kv.x, kv.y, kv.z, kv.w};
            #pragma unroll
            for (int i = 0; i < 4; i++)
                #pragma unroll
                for (int j = 0; j < 4; j++)
                    s_[i][j] += qa[i] * ka[j];
        }

        #pragma unroll
        for (int i = 0; i < 4; i++) {
            float e[4] = {e2v[i].x, e2v[i].y, e2v[i].z, e2v[i].w};
            int   mm[4] = {mk[i].x, mk[i].y, mk[i].z, mk[i].w};
            #pragma unroll
            for (int j = 0; j < 4; j++) {
                float v = s_[i][j] * 0.125f + e[j];
                s_[i][j] = mm[j] ? -1e8f : v;
            }
        }

        // online softmax (rows owned by same (ty,i); shuffles stay in 16-lane half)
        #pragma unroll
        for (int i = 0; i < 4; i++) {
            float tm = fmaxf(fmaxf(s_[i][0], s_[i][1]), fmaxf(s_[i][2], s_[i][3]));
            #pragma unroll
            for (int w = 8; w >= 1; w >>= 1)
                tm = fmaxf(tm, __shfl_xor_sync(0xffffffffu, tm, w));
            float mn = fmaxf(m_[i], tm);
            float sc = __expf(m_[i] - mn);
            m_[i] = mn;
            float ts = 0.f;
            #pragma unroll
            for (int j = 0; j < 4; j++) {
                float p = __expf(s_[i][j] - mn);
                s_[i][j] = p;
                ts += p;
            }
            #pragma unroll
            for (int w = 8; w >= 1; w >>= 1)
                ts += __shfl_xor_sync(0xffffffffu, ts, w);
            l_[i] = l_[i] * sc + ts;
            #pragma unroll
            for (int j = 0; j < 4; j++) o_[i][j] *= sc;
            *(float4*)&Ssm[((ty << 2) + i) * 68 + (tx << 2)] =
                make_float4(s_[i][0], s_[i][1], s_[i][2], s_[i][3]);
        }
        __syncthreads();

        // P @ V
        #pragma unroll 16
        for (int k = 0; k < 64; k++) {
            float4 vv = *(const float4*)&Vs[(k << 6) + (tx << 2)];
            float va[4] = {vv.x, vv.y, vv.z, vv.w};
            #pragma unroll
            for (int i = 0; i < 4; i++) {
                float p = Ssm[((ty << 2) + i) * 68 + k];
                #pragma unroll
                for (int j = 0; j < 4; j++)
                    o_[i][j] += p * va[j];
            }
        }
    }

    #pragma unroll
    for (int i = 0; i < 4; i++) {
        float inv = 1.0f / l_[i];
        int q = q0 + (ty << 2) + i;
        float4 ov = make_float4(o_[i][0] * inv, o_[i][1] * inv,
                                o_[i][2] * inv, o_[i][3] * inv);
        *(float4*)&out[((size_t)b * SEQ + q) * DMOD + h * DK + (tx << 2)] = ov;
    }
}

// ---------------------------------------------------------------------------
extern "C" void kernel_launch(void* const* d_in, const int* in_sizes, int n_in,
                              void* d_out, int out_size)
{
    const float* query = (const float*)d_in[0];
    const float* key   = (const float*)d_in[1];
    const float* value = (const float*)d_in[2];
    const float* rel   = (const float*)d_in[3];
    const float* W_q   = (const float*)d_in[4];
    const float* b_q   = (const float*)d_in[5];
    const float* W_k   = (const float*)d_in[6];
    const float* b_k   = (const float*)d_in[7];
    const float* W_v   = (const float*)d_in[8];
    const float* b_v   = (const float*)d_in[9];
    const int*   mask  = (const int*)d_in[10];
    float* out = (float*)d_out;

    cudaFuncSetAttribute(attn_kernel,
                         cudaFuncAttributeMaxDynamicSharedMemorySize,
                         ATTN_SMEM_BYTES);

    dim3 pg(DMOD / 64, (BB * SEQ) / 64);                 // (16, 128)
    proj_kernel<<<pg, 256>>>(query, W_q, b_q, 0);
    proj_kernel<<<pg, 256>>>(key,   W_k, b_k, 1);
    proj_kernel<<<pg, 256>>>(value, W_v, b_v, 2);

    e2_kernel<<<dim3(SEQ / 64, SEQ), 256>>>(rel);        // (16, 1024)

    attn_kernel<<<dim3(SEQ / 64, NBH), 256, ATTN_SMEM_BYTES>>>(mask, out);
}

// round 4
// speedup vs baseline: 1.2207x; 1.2207x over previous
#include <cuda_runtime.h>
#include <cuda_bf16.h>
#include <cstdint>

#define BB   8
#define SEQ  1024
#define DMOD 1024
#define NH   16
#define DK   64
#define NBH  128   // BB*NH

// Scratch (device globals — allocation-free per harness rules)
__device__ float g_Q[(size_t)NBH * SEQ * DK];           // [bh][s][d]  33.5MB
__device__ float g_K[(size_t)NBH * SEQ * DK];
__device__ float g_V[(size_t)NBH * SEQ * DK];
__device__ float g_E2[(size_t)NBH * SEQ * SEQ];         // [bh][q][k]  512MB

// ---------------------------------------------------------------------------
// Warp-MMA helpers (portable PTX: ldmatrix + mma.sync, no tcgen05)
// ---------------------------------------------------------------------------
__device__ __forceinline__ uint32_t smem_u32(const void* p) {
    uint32_t a;
    asm("{ .reg .u64 t; cvta.to.shared.u64 t, %1; cvt.u32.u64 %0, t; }"
        : "=r"(a) : "l"(p));
    return a;
}

__device__ __forceinline__ void ldsm_x4(uint32_t* r, uint32_t addr) {
    asm volatile("ldmatrix.sync.aligned.m8n8.x4.shared.b16 {%0,%1,%2,%3}, [%4];"
                 : "=r"(r[0]), "=r"(r[1]), "=r"(r[2]), "=r"(r[3]) : "r"(addr));
}

__device__ __forceinline__ void mma_bf16(float* d, const uint32_t* a,
                                         uint32_t b0, uint32_t b1) {
    asm volatile(
        "mma.sync.aligned.m16n8k16.row.col.f32.bf16.bf16.f32 "
        "{%0,%1,%2,%3}, {%4,%5,%6,%7}, {%8,%9}, {%0,%1,%2,%3};"
        : "+f"(d[0]), "+f"(d[1]), "+f"(d[2]), "+f"(d[3])
        : "r"(a[0]), "r"(a[1]), "r"(a[2]), "r"(a[3]), "r"(b0), "r"(b1));
}

__device__ __forceinline__ void split_pack(float x0, float x1,
                                           uint32_t& wh, uint32_t& wl) {
    __nv_bfloat16 h0 = __float2bfloat16_rn(x0);
    __nv_bfloat16 h1 = __float2bfloat16_rn(x1);
    __nv_bfloat16 l0 = __float2bfloat16_rn(x0 - __bfloat162float(h0));
    __nv_bfloat16 l1 = __float2bfloat16_rn(x1 - __bfloat162float(h1));
    wh = (uint32_t)*(unsigned short*)&h0 | ((uint32_t)*(unsigned short*)&h1 << 16);
    wl = (uint32_t)*(unsigned short*)&l0 | ((uint32_t)*(unsigned short*)&l1 << 16);
}

// ---------------------------------------------------------------------------
// Projection GEMM via mma.sync bf16x3: C = X·W + b, fp32-equivalent.
// CTA tile M=128,N=128; K-chunks of 64; double-buffered smem (128B rows,
// SW128-style XOR swizzle -> conflict-free ldmatrix). 8 warps = 2(M)x4(N).
// ---------------------------------------------------------------------------
#define PROJ_SEG   16384                       // 128 rows x 128B (64 bf16)
#define PROJ_STAGE (4 * PROJ_SEG)              // Ah, Al, Bh, Bl
#define PROJ_SMEM  (2 * PROJ_STAGE + 1024)
#define NCHUNK     16

__global__ __launch_bounds__(256, 1)
void proj_tc_kernel(const float* __restrict__ Xq, const float* __restrict__ Xk,
                    const float* __restrict__ Xv,
                    const float* __restrict__ Wq, const float* __restrict__ Wk,
                    const float* __restrict__ Wv,
                    const float* __restrict__ bq, const float* __restrict__ bk,
                    const float* __restrict__ bv)
{
    extern __shared__ char dsm[];
    __shared__ float sbias[128];

    const int t   = threadIdx.x;
    const int wid = t >> 5, lid = t & 31;
    const int n0  = blockIdx.x * 128;
    const int m0  = blockIdx.y * 128;
    const int pz  = blockIdx.z;

    const float* X = (pz == 0) ? Xq : (pz == 1) ? Xk : Xv;
    const float* W = (pz == 0) ? Wq : (pz == 1) ? Wk : Wv;
    const float* bias = (pz == 0) ? bq : (pz == 1) ? bk : bv;
    float* outg = (pz == 0) ? g_Q : (pz == 1) ? g_K : g_V;

    uint32_t raw = smem_u32(dsm);
    uint32_t pad = (1024u - (raw & 1023u)) & 1023u;
    char* base = dsm + pad;
    uint32_t base_a = raw + pad;

    if (t < 128) sbias[t] = bias[n0 + t];

    // loader mappings
    const int ar = t >> 1, akh = (t & 1) << 5;      // A: row, k-half
    const int bn = t & 127, bkb = (t >> 7) << 5;    // B: n, k-base (32 k each)

    // warp tiling: 2(M) x 4(N)
    const int wm = wid & 1, wn = wid >> 1;
    const int sub = lid >> 3, rsub = lid & 7;
    const int frow = ((sub & 1) << 3) + rsub;       // row within 16-row tile
    const int fkg  = sub >> 1;                      // k-group (0/1) within k16

    // per-lane ldmatrix row offsets (bytes), swizzle XOR = rsub<<4
    const uint32_t a_row_off = (uint32_t)(wm * 64 + frow) * 128u;
    const uint32_t b_row_off = (uint32_t)(wn * 32 + frow) * 128u;
    const uint32_t sx = (uint32_t)rsub << 4;

    float acc[4][4][4];
    #pragma unroll
    for (int i = 0; i < 4; i++)
        #pragma unroll
        for (int j = 0; j < 4; j++)
            #pragma unroll
            for (int k = 0; k < 4; k++) acc[i][j][k] = 0.f;

    uint32_t Ahw[16], Alw[16], Bhw[16], Blw[16];

    // ---- global load into regs (chunk c) ----
    auto load_regs = [&](int c) {
        const float* ag = X + (size_t)(m0 + ar) * DMOD + c * 64 + akh;
        #pragma unroll
        for (int i = 0; i < 8; i++) {
            float4 v = *(const float4*)&ag[i * 4];
            split_pack(v.x, v.y, Ahw[2 * i + 0], Alw[2 * i + 0]);
            split_pack(v.z, v.w, Ahw[2 * i + 1], Alw[2 * i + 1]);
        }
        const float* bg = W + (size_t)(c * 64 + bkb) * DMOD + n0 + bn;
        #pragma unroll
        for (int i = 0; i < 16; i++) {
            float x0 = bg[(size_t)(2 * i) * DMOD];
            float x1 = bg[(size_t)(2 * i + 1) * DMOD];
            split_pack(x0, x1, Bhw[i], Blw[i]);
        }
    };

    // ---- store staged regs into smem stage ----
    auto store_regs = [&](int stage) {
        char* Ah = base + stage * PROJ_STAGE;
        char* Al = Ah + PROJ_SEG;
        char* Bh = Al + PROJ_SEG;
        char* Bl = Bh + PROJ_SEG;
        #pragma unroll
        for (int g = 0; g < 4; g++) {
            uint32_t bo = (uint32_t)(akh * 2 + g * 16);
            uint32_t po = (uint32_t)ar * 128u + (bo ^ (((uint32_t)ar & 7u) << 4));
            *(uint4*)(Ah + po) = make_uint4(Ahw[4*g], Ahw[4*g+1], Ahw[4*g+2], Ahw[4*g+3]);
            *(uint4*)(Al + po) = make_uint4(Alw[4*g], Alw[4*g+1], Alw[4*g+2], Alw[4*g+3]);
        }
        #pragma unroll
        for (int g = 0; g < 4; g++) {
            uint32_t bo = (uint32_t)(bkb * 2 + g * 16);
            uint32_t po = (uint32_t)bn * 128u + (bo ^ (((uint32_t)bn & 7u) << 4));
            *(uint4*)(Bh + po) = make_uint4(Bhw[4*g], Bhw[4*g+1], Bhw[4*g+2], Bhw[4*g+3]);
            *(uint4*)(Bl + po) = make_uint4(Blw[4*g], Blw[4*g+1], Blw[4*g+2], Blw[4*g+3]);
        }
    };

    // ---- MMA over one 64-k stage ----
    auto mma_stage = [&](int stage) {
        uint32_t AhB = base_a + stage * PROJ_STAGE + a_row_off;
        uint32_t AlB = AhB + PROJ_SEG;
        uint32_t BhB = base_a + stage * PROJ_STAGE + 2 * PROJ_SEG + b_row_off;
        uint32_t BlB = BhB + PROJ_SEG;
        #pragma unroll
        for (int ks = 0; ks < 4; ks++) {
            uint32_t koff = (uint32_t)(ks * 32 + fkg * 16) ^ sx;
            uint32_t ah[4][4], al[4][4];
            #pragma unroll
            for (int mt = 0; mt < 4; mt++) {
                ldsm_x4(ah[mt], AhB + mt * 2048 + koff);
                ldsm_x4(al[mt], AlB + mt * 2048 + koff);
            }
            uint32_t bh[8], bl[8];
            ldsm_x4(bh + 0, BhB + koff);
            ldsm_x4(bh + 4, BhB + 2048 + koff);
            ldsm_x4(bl + 0, BlB + koff);
            ldsm_x4(bl + 4, BlB + 2048 + koff);
            // n-tile nt: regs {r0,r2} of call nt>>1 when (nt&1)==0 else {r1,r3}
            #pragma unroll
            for (int mt = 0; mt < 4; mt++) {
                #pragma unroll
                for (int nt = 0; nt < 4; nt++) {
                    int cb = (nt >> 1) * 4, od = nt & 1;
                    uint32_t b0h = bh[cb + od], b1h = bh[cb + od + 2];
                    uint32_t b0l = bl[cb + od], b1l = bl[cb + od + 2];
                    mma_bf16(acc[mt][nt], ah[mt], b0h, b1h);
                    mma_bf16(acc[mt][nt], ah[mt], b0l, b1l);
                    mma_bf16(acc[mt][nt], al[mt], b0h, b1h);
                }
            }
        }
    };

    load_regs(0);
    store_regs(0);
    __syncthreads();

    for (int c = 0; c < NCHUNK; c++) {
        if (c + 1 < NCHUNK) load_regs(c + 1);
        mma_stage(c & 1);
        __syncthreads();
        if (c + 1 < NCHUNK) {
            store_regs((c + 1) & 1);
            __syncthreads();
        }
    }

    // ---- epilogue: fragments -> g_{Q,K,V} [bh][s][d] with bias ----
    const int g  = lid >> 2, t4 = lid & 3;
    #pragma unroll
    for (int mt = 0; mt < 4; mt++) {
        int r0 = m0 + wm * 64 + mt * 16 + g;
        #pragma unroll
        for (int half = 0; half < 2; half++) {
            int m = r0 + half * 8;
            int b = m >> 10, s = m & (SEQ - 1);
            #pragma unroll
            for (int nt = 0; nt < 4; nt++) {
                int nl = wn * 32 + nt * 8 + 2 * t4;
                int h  = (n0 >> 6) + (nl >> 6);
                int d  = nl & 63;
                float* op = outg + (((size_t)(b * NH + h)) * SEQ + s) * DK + d;
                float2 v;
                v.x = acc[mt][nt][2 * half + 0] + sbias[nl + 0];
                v.y = acc[mt][nt][2 * half + 1] + sbias[nl + 1];
                *(float2*)op = v;
            }
        }
    }
}

// ---------------------------------------------------------------------------
// E2[bh][q][k] = sum_d Q[bh][q][d] * rel[q][k][d]   (unchanged, passing)
// ---------------------------------------------------------------------------
__global__ __launch_bounds__(256, 3)
void e2_kernel(const float* __restrict__ rel)
{
    __shared__ float Qst[64 * 128];
    __shared__ float Rst[64 * 64];
    const int t  = threadIdx.x;
    const int tx = t & 15, ty = t >> 4;
    const int q  = blockIdx.y;
    const int k0 = blockIdx.x * 64;

    #pragma unroll
    for (int p = 0; p < 32; p++) {
        int idx = p * 256 + t;
        int bh = idx >> 6, d = idx & 63;
        Qst[(d << 7) + ((((bh >> 2) ^ (d & 15)) << 2) | (bh & 3))] =
            g_Q[((size_t)bh * SEQ + q) * DK + d];
    }
    const float* rbase = rel + ((size_t)q * SEQ + k0) * DK;
    #pragma unroll
    for (int p = 0; p < 16; p++) {
        int idx = p * 256 + t;
        int kk = idx >> 6, d = idx & 63;
        Rst[(d << 6) + ((((kk >> 2) ^ (d & 15)) << 2) | (kk & 3))] = rbase[idx];
    }
    __syncthreads();

    float acc[8][4] = {};
    #pragma unroll 16
    for (int d = 0; d < 64; d++) {
        int sw = d & 15;
        float4 a0 = *(const float4*)&Qst[(d << 7) + ((ty ^ sw) << 2)];
        float4 a1 = *(const float4*)&Qst[(d << 7) + (((16 + ty) ^ sw) << 2)];
        float4 bq = *(const float4*)&Rst[(d << 6) + ((tx ^ sw) << 2)];
        float as[8] = {a0.x, a0.y, a0.z, a0.w, a1.x, a1.y, a1.z, a1.w};
        float bs[4] = {bq.x, bq.y, bq.z, bq.w};
        #pragma unroll
        for (int i = 0; i < 8; i++)
            #pragma unroll
            for (int j = 0; j < 4; j++)
                acc[i][j] += as[i] * bs[j];
    }

    #pragma unroll
    for (int i = 0; i < 8; i++) {
        int bh = (i < 4) ? (ty << 2) + i : 64 + (ty << 2) + (i - 4);
        size_t o = ((size_t)bh * SEQ + q) * SEQ + k0 + (tx << 2);
        *(float4*)&g_E2[o] = make_float4(acc[i][0], acc[i][1], acc[i][2], acc[i][3]);
    }
}

// ---------------------------------------------------------------------------
// Fused attention (unchanged, passing). mask is int32 (jax bool -> int32).
// ---------------------------------------------------------------------------
#define ATTN_SMEM_FLOATS (64 * 64 * 3 + 64 * 68)
#define ATTN_SMEM_BYTES  (ATTN_SMEM_FLOATS * 4)

__global__ __launch_bounds__(256, 2)
void attn_kernel(const int* __restrict__ mask, float* __restrict__ out)
{
    extern __shared__ float sm[];
    float* Qst = sm;
    float* Kst = sm + 4096;
    float* Vs  = sm + 8192;
    float* Ssm = sm + 12288;

    const int t  = threadIdx.x;
    const int tx = t & 15, ty = t >> 4;
    const int q0 = blockIdx.x * 64;
    const int bh = blockIdx.y;
    const int b  = bh >> 4, h = bh & 15;

    const float* qg = g_Q + ((size_t)bh * SEQ + q0) * DK;
    #pragma unroll
    for (int p = 0; p < 16; p++) {
        int idx = p * 256 + t;
        int c = idx >> 6, d = idx & 63;
        Qst[(d << 6) + ((((c >> 2) ^ (d & 15)) << 2) | (c & 3))] = qg[idx];
    }

    float m_[4], l_[4], o_[4][4];
    #pragma unroll
    for (int i = 0; i < 4; i++) {
        m_[i] = -1e30f; l_[i] = 0.f;
        #pragma unroll
        for (int j = 0; j < 4; j++) o_[i][j] = 0.f;
    }

    const float* kg  = g_K + (size_t)bh * SEQ * DK;
    const float* vg  = g_V + (size_t)bh * SEQ * DK;
    const float* e2g = g_E2 + ((size_t)bh * SEQ + q0) * SEQ;
    const int*   mg  = mask + ((size_t)b * SEQ + q0) * SEQ;

    for (int kt = 0; kt < SEQ; kt += 64) {
        __syncthreads();
        const float* kgt = kg + (size_t)kt * DK;
        #pragma unroll
        for (int p = 0; p < 16; p++) {
            int idx = p * 256 + t;
            int c = idx >> 6, d = idx & 63;
            Kst[(d << 6) + ((((c >> 2) ^ (d & 15)) << 2) | (c & 3))] = kgt[idx];
        }
        const float* vgt = vg + (size_t)kt * DK;
        #pragma unroll
        for (int p = 0; p < 4; p++) {
            int idx = (p * 256 + t) << 2;
            *(float4*)&Vs[idx] = *(const float4*)&vgt[idx];
        }
        __syncthreads();

        float4 e2v[4];
        int4   mk[4];
        #pragma unroll
        for (int i = 0; i < 4; i++) {
            int r = (ty << 2) + i;
            e2v[i] = *(const float4*)&e2g[(size_t)r * SEQ + kt + (tx << 2)];
            mk[i]  = *(const int4*)&mg[(size_t)r * SEQ + kt + (tx << 2)];
        }

        float s_[4][4] = {};
        #pragma unroll 16
        for (int d = 0; d < 64; d++) {
            int sw = d & 15;
            float4 qv = *(const float4*)&Qst[(d << 6) + ((ty ^ sw) << 2)];
            float4 kv = *(const float4*)&Kst[(d << 6) + ((tx ^ sw) << 2)];
            float qa[4] = {qv.x, qv.y, qv.z, qv.w};
            float ka[4] = {kv.x, kv.y, kv.z, kv.w};
            #pragma unroll
            for (int i = 0; i < 4; i++)
                #pragma unroll
                for (int j = 0; j < 4; j++)
                    s_[i][j] += qa[i] * ka[j];
        }

        #pragma unroll
        for (int i = 0; i < 4; i++) {
            float e[4] = {e2v[i].x, e2v[i].y, e2v[i].z, e2v[i].w};
            int   mm[4] = {mk[i].x, mk[i].y, mk[i].z, mk[i].w};
            #pragma unroll
            for (int j = 0; j < 4; j++) {
                float v = s_[i][j] * 0.125f + e[j];
                s_[i][j] = mm[j] ? -1e8f : v;
            }
        }

        #pragma unroll
        for (int i = 0; i < 4; i++) {
            float tm = fmaxf(fmaxf(s_[i][0], s_[i][1]), fmaxf(s_[i][2], s_[i][3]));
            #pragma unroll
            for (int w = 8; w >= 1; w >>= 1)
                tm = fmaxf(tm, __shfl_xor_sync(0xffffffffu, tm, w));
            float mn = fmaxf(m_[i], tm);
            float sc = __expf(m_[i] - mn);
            m_[i] = mn;
            float ts = 0.f;
            #pragma unroll
            for (int j = 0; j < 4; j++) {
                float p = __expf(s_[i][j] - mn);
                s_[i][j] = p;
                ts += p;
            }
            #pragma unroll
            for (int w = 8; w >= 1; w >>= 1)
                ts += __shfl_xor_sync(0xffffffffu, ts, w);
            l_[i] = l_[i] * sc + ts;
            #pragma unroll
            for (int j = 0; j < 4; j++) o_[i][j] *= sc;
            *(float4*)&Ssm[((ty << 2) + i) * 68 + (tx << 2)] =
                make_float4(s_[i][0], s_[i][1], s_[i][2], s_[i][3]);
        }
        __syncthreads();

        #pragma unroll 16
        for (int k = 0; k < 64; k++) {
            float4 vv = *(const float4*)&Vs[(k << 6) + (tx << 2)];
            float va[4] = {vv.x, vv.y, vv.z, vv.w};
            #pragma unroll
            for (int i = 0; i < 4; i++) {
                float p = Ssm[((ty << 2) + i) * 68 + k];
                #pragma unroll
                for (int j = 0; j < 4; j++)
                    o_[i][j] += p * va[j];
            }
        }
    }

    #pragma unroll
    for (int i = 0; i < 4; i++) {
        float inv = 1.0f / l_[i];
        int q = q0 + (ty << 2) + i;
        float4 ov = make_float4(o_[i][0] * inv, o_[i][1] * inv,
                                o_[i][2] * inv, o_[i][3] * inv);
        *(float4*)&out[((size_t)b * SEQ + q) * DMOD + h * DK + (tx << 2)] = ov;
    }
}

// ---------------------------------------------------------------------------
extern "C" void kernel_launch(void* const* d_in, const int* in_sizes, int n_in,
                              void* d_out, int out_size)
{
    const float* query = (const float*)d_in[0];
    const float* key   = (const float*)d_in[1];
    const float* value = (const float*)d_in[2];
    const float* rel   = (const float*)d_in[3];
    const float* W_q   = (const float*)d_in[4];
    const float* b_q   = (const float*)d_in[5];
    const float* W_k   = (const float*)d_in[6];
    const float* b_k   = (const float*)d_in[7];
    const float* W_v   = (const float*)d_in[8];
    const float* b_v   = (const float*)d_in[9];
    const int*   mask  = (const int*)d_in[10];
    float* out = (float*)d_out;

    cudaFuncSetAttribute(proj_tc_kernel,
                         cudaFuncAttributeMaxDynamicSharedMemorySize,
                         PROJ_SMEM);
    cudaFuncSetAttribute(attn_kernel,
                         cudaFuncAttributeMaxDynamicSharedMemorySize,
                         ATTN_SMEM_BYTES);

    proj_tc_kernel<<<dim3(DMOD / 128, (BB * SEQ) / 128, 3), 256, PROJ_SMEM>>>(
        query, key, value, W_q, W_k, W_v, b_q, b_k, b_v);

    e2_kernel<<<dim3(SEQ / 64, SEQ), 256>>>(rel);        // (16, 1024)

    attn_kernel<<<dim3(SEQ / 64, NBH), 256, ATTN_SMEM_BYTES>>>(mask, out);
}

// round 5
// speedup vs baseline: 1.6862x; 1.3814x over previous
#include <cuda_runtime.h>
#include <cuda_bf16.h>
#include <cstdint>

#define BB   8
#define SEQ  1024
#define DMOD 1024
#define NH   16
#define DK   64
#define NBH  128   // BB*NH

// Scratch (device globals — allocation-free per harness rules)
__device__ float g_Q[(size_t)NBH * SEQ * DK];
__device__ float g_K[(size_t)NBH * SEQ * DK];
__device__ float g_V[(size_t)NBH * SEQ * DK];
__device__ float g_E2[(size_t)NBH * SEQ * SEQ];          // [bh][q][k] 512MB

__device__ __nv_bfloat16 g_Xh[3ull * 8192 * 1024];       // inputs hi/lo
__device__ __nv_bfloat16 g_Xl[3ull * 8192 * 1024];
__device__ __nv_bfloat16 g_Wth[3ull * 1024 * 1024];      // W^T hi/lo [n][k]
__device__ __nv_bfloat16 g_Wtl[3ull * 1024 * 1024];
__device__ __nv_bfloat16 g_Qh[(size_t)NBH * SEQ * DK];   // Q bf16 hi/lo
__device__ __nv_bfloat16 g_Ql[(size_t)NBH * SEQ * DK];

// ---------------------------------------------------------------------------
// Helpers
// ---------------------------------------------------------------------------
__device__ __forceinline__ uint32_t smem_u32(const void* p) {
    uint32_t a;
    asm("{ .reg .u64 t; cvta.to.shared.u64 t, %1; cvt.u32.u64 %0, t; }"
        : "=r"(a) : "l"(p));
    return a;
}
__device__ __forceinline__ void ldsm_x4(uint32_t* r, uint32_t addr) {
    asm volatile("ldmatrix.sync.aligned.m8n8.x4.shared.b16 {%0,%1,%2,%3}, [%4];"
                 : "=r"(r[0]), "=r"(r[1]), "=r"(r[2]), "=r"(r[3]) : "r"(addr));
}
__device__ __forceinline__ void mma_bf16(float* d, const uint32_t* a,
                                         uint32_t b0, uint32_t b1) {
    asm volatile(
        "mma.sync.aligned.m16n8k16.row.col.f32.bf16.bf16.f32 "
        "{%0,%1,%2,%3}, {%4,%5,%6,%7}, {%8,%9}, {%0,%1,%2,%3};"
        : "+f"(d[0]), "+f"(d[1]), "+f"(d[2]), "+f"(d[3])
        : "r"(a[0]), "r"(a[1]), "r"(a[2]), "r"(a[3]), "r"(b0), "r"(b1));
}
__device__ __forceinline__ void split_pack(float x0, float x1,
                                           uint32_t& wh, uint32_t& wl) {
    __nv_bfloat16 h0 = __float2bfloat16_rn(x0);
    __nv_bfloat16 h1 = __float2bfloat16_rn(x1);
    __nv_bfloat16 l0 = __float2bfloat16_rn(x0 - __bfloat162float(h0));
    __nv_bfloat16 l1 = __float2bfloat16_rn(x1 - __bfloat162float(h1));
    wh = (uint32_t)*(unsigned short*)&h0 | ((uint32_t)*(unsigned short*)&h1 << 16);
    wl = (uint32_t)*(unsigned short*)&l0 | ((uint32_t)*(unsigned short*)&l1 << 16);
}
__device__ __forceinline__ void cp16(uint32_t dst, const void* src) {
    asm volatile("cp.async.cg.shared.global [%0], [%1], 16;"
                 :: "r"(dst), "l"(src));
}
#define CP_COMMIT() asm volatile("cp.async.commit_group;" ::: "memory")
#define CP_WAIT1()  asm volatile("cp.async.wait_group 1;" ::: "memory")
#define CP_WAIT0()  asm volatile("cp.async.wait_group 0;" ::: "memory")

// ---------------------------------------------------------------------------
// Pre-conversion kernels
// ---------------------------------------------------------------------------
__global__ __launch_bounds__(256)
void conv_x_kernel(const float* __restrict__ xq, const float* __restrict__ xk,
                   const float* __restrict__ xv)
{
    const int pz = blockIdx.y;
    const float* X = (pz == 0) ? xq : (pz == 1) ? xk : xv;
    size_t i4 = ((size_t)blockIdx.x * 256 + threadIdx.x) * 4;
    float4 v = *(const float4*)(X + i4);
    uint32_t h0, l0, h1, l1;
    split_pack(v.x, v.y, h0, l0);
    split_pack(v.z, v.w, h1, l1);
    size_t base = (size_t)pz * (8192ull * 1024) + i4;
    *(uint2*)&g_Xh[base] = make_uint2(h0, h1);
    *(uint2*)&g_Xl[base] = make_uint2(l0, l1);
}

__global__ __launch_bounds__(256)
void conv_w_kernel(const float* __restrict__ wq, const float* __restrict__ wk,
                   const float* __restrict__ wv)
{
    __shared__ float sm[32][33];
    const int pz = blockIdx.z;
    const float* W = (pz == 0) ? wq : (pz == 1) ? wk : wv;
    const int n0 = blockIdx.x * 32, k0 = blockIdx.y * 32;
    const int t = threadIdx.x, r = t >> 5, c = t & 31;
    #pragma unroll
    for (int i = 0; i < 4; i++)
        sm[r + i * 8][c] = W[(size_t)(k0 + r + i * 8) * DMOD + n0 + c];
    __syncthreads();
    size_t base = (size_t)pz * (1024ull * 1024);
    #pragma unroll
    for (int i = 0; i < 4; i++) {
        int n = r + i * 8;
        float x = sm[c][n];
        __nv_bfloat16 h = __float2bfloat16_rn(x);
        __nv_bfloat16 l = __float2bfloat16_rn(x - __bfloat162float(h));
        g_Wth[base + (size_t)(n0 + n) * DMOD + k0 + c] = h;
        g_Wtl[base + (size_t)(n0 + n) * DMOD + k0 + c] = l;
    }
}

// ---------------------------------------------------------------------------
// Projection GEMM (bf16x3, cp.async pipelined). CTA tile M=128 x N=64, K=64
// per stage, 2 stages. 8 warps = 4(M) x 2(N), warp tile 32x32.
// ---------------------------------------------------------------------------
#define PROJ_STAGE 49152       // Ah 16K | Al 16K | Bh 8K | Bl 8K
#define PROJ_SMEM  (2 * PROJ_STAGE + 1024)
#define NCHUNK     16

__global__ __launch_bounds__(256, 2)
void proj_tc_kernel(const float* __restrict__ bq, const float* __restrict__ bk,
                    const float* __restrict__ bv)
{
    extern __shared__ char dsm[];
    __shared__ float sbias[64];

    const int t = threadIdx.x, wid = t >> 5, lid = t & 31;
    const int n0 = blockIdx.x * 64;
    const int m0 = blockIdx.y * 128;
    const int pz = blockIdx.z;

    const float* bias = (pz == 0) ? bq : (pz == 1) ? bk : bv;
    float* outg = (pz == 0) ? g_Q : (pz == 1) ? g_K : g_V;
    const __nv_bfloat16* Xh = g_Xh + (size_t)pz * (8192ull * 1024);
    const __nv_bfloat16* Xl = g_Xl + (size_t)pz * (8192ull * 1024);
    const __nv_bfloat16* Wh = g_Wth + (size_t)pz * (1024ull * 1024);
    const __nv_bfloat16* Wl = g_Wtl + (size_t)pz * (1024ull * 1024);

    uint32_t raw = smem_u32(dsm);
    uint32_t pad = (1024u - (raw & 1023u)) & 1023u;
    uint32_t base_a = raw + pad;

    if (t < 64) sbias[t] = bias[n0 + t];

    auto issue = [&](int c, int st) {
        uint32_t S = base_a + st * PROJ_STAGE;
        #pragma unroll
        for (int i = 0; i < 4; i++) {
            int idx = i * 256 + t, row = idx >> 3, g = idx & 7;
            uint32_t d = S + row * 128 + (uint32_t)((g ^ (row & 7)) << 4);
            size_t so = (size_t)(m0 + row) * DMOD + c * 64 + g * 8;
            cp16(d, Xh + so);
            cp16(d + 16384, Xl + so);
        }
        #pragma unroll
        for (int i = 0; i < 2; i++) {
            int idx = i * 256 + t, row = idx >> 3, g = idx & 7;
            uint32_t d = S + 32768 + row * 128 + (uint32_t)((g ^ (row & 7)) << 4);
            size_t so = (size_t)(n0 + row) * DMOD + c * 64 + g * 8;
            cp16(d, Wh + so);
            cp16(d + 8192, Wl + so);
        }
        CP_COMMIT();
    };

    const int wm = wid & 3, wn = wid >> 2;
    const int sub = lid >> 3, rsub = lid & 7;
    const int frow = ((sub & 1) << 3) + rsub;
    const int fkg = sub >> 1;
    const uint32_t sx = (uint32_t)rsub << 4;
    const uint32_t a_off = (uint32_t)(wm * 32 + frow) * 128u;
    const uint32_t b_off = (uint32_t)(wn * 32 + frow) * 128u;

    float acc[2][4][4];
    #pragma unroll
    for (int i = 0; i < 2; i++)
        #pragma unroll
        for (int j = 0; j < 4; j++)
            #pragma unroll
            for (int k = 0; k < 4; k++) acc[i][j][k] = 0.f;

    auto mma_stage = [&](int st) {
        uint32_t S = base_a + st * PROJ_STAGE;
        uint32_t AhB = S + a_off, AlB = AhB + 16384;
        uint32_t BhB = S + 32768 + b_off, BlB = BhB + 8192;
        #pragma unroll
        for (int ks = 0; ks < 4; ks++) {
            uint32_t koff = ((uint32_t)(ks * 32 + fkg * 16)) ^ sx;
            uint32_t ah[2][4], al[2][4], bhf[8], blf[8];
            #pragma unroll
            for (int mt = 0; mt < 2; mt++) {
                ldsm_x4(ah[mt], AhB + mt * 2048 + koff);
                ldsm_x4(al[mt], AlB + mt * 2048 + koff);
            }
            ldsm_x4(bhf + 0, BhB + koff);
            ldsm_x4(bhf + 4, BhB + 2048 + koff);
            ldsm_x4(blf + 0, BlB + koff);
            ldsm_x4(blf + 4, BlB + 2048 + koff);
            #pragma unroll
            for (int mt = 0; mt < 2; mt++)
                #pragma unroll
                for (int nt = 0; nt < 4; nt++) {
                    int cb = (nt >> 1) * 4, od = nt & 1;
                    mma_bf16(acc[mt][nt], ah[mt], bhf[cb + od], bhf[cb + od + 2]);
                    mma_bf16(acc[mt][nt], ah[mt], blf[cb + od], blf[cb + od + 2]);
                    mma_bf16(acc[mt][nt], al[mt], bhf[cb + od], bhf[cb + od + 2]);
                }
        }
    };

    issue(0, 0);
    issue(1, 1);
    for (int c = 0; c < NCHUNK; c++) {
        if (c < NCHUNK - 1) CP_WAIT1(); else CP_WAIT0();
        __syncthreads();
        mma_stage(c & 1);
        if (c + 2 < NCHUNK) {
            __syncthreads();
            issue(c + 2, c & 1);
        }
    }

    // epilogue
    const int g = lid >> 2, t4 = lid & 3;
    const int h = blockIdx.x;
    #pragma unroll
    for (int mt = 0; mt < 2; mt++)
        #pragma unroll
        for (int half = 0; half < 2; half++) {
            int m = m0 + wm * 32 + mt * 16 + g + half * 8;
            int b = m >> 10, s = m & (SEQ - 1);
            #pragma unroll
            for (int nt = 0; nt < 4; nt++) {
                int d = wn * 32 + nt * 8 + 2 * t4;
                size_t off = (((size_t)(b * NH + h)) * SEQ + s) * DK + d;
                float2 v;
                v.x = acc[mt][nt][2 * half + 0] + sbias[d];
                v.y = acc[mt][nt][2 * half + 1] + sbias[d + 1];
                *(float2*)(outg + off) = v;
                if (pz == 0) {
                    uint32_t wh, wl;
                    split_pack(v.x, v.y, wh, wl);
                    *(uint32_t*)&g_Qh[off] = wh;
                    *(uint32_t*)&g_Ql[off] = wl;
                }
            }
        }
}

// ---------------------------------------------------------------------------
// E2 via mma.sync bf16x3: per block one q; M=128(bh) x N=64(k-tile) x K=64(d).
// Q from g_Qh/g_Ql (cp.async), rel converted in-flight, read once.
// ---------------------------------------------------------------------------
#define E2_RSTG  16384         // Rh 8K | Rl 8K
#define E2_SMEM  (32768 + 2 * E2_RSTG + 1024)

__global__ __launch_bounds__(256, 2)
void e2_tc_kernel(const float* __restrict__ rel)
{
    extern __shared__ char dsm[];
    const int t = threadIdx.x, wid = t >> 5, lid = t & 31;
    const int q = blockIdx.x;

    uint32_t raw = smem_u32(dsm);
    uint32_t pad = (1024u - (raw & 1023u)) & 1023u;
    char* basec = dsm + pad;
    uint32_t base_a = raw + pad;
    uint32_t Qa = base_a;             // Qh 16K, Ql +16384
    uint32_t Ra = base_a + 32768;     // stages

    // Q tiles via cp.async
    #pragma unroll
    for (int i = 0; i < 4; i++) {
        int idx = i * 256 + t, row = idx >> 3, g = idx & 7;
        uint32_t d = Qa + row * 128 + (uint32_t)((g ^ (row & 7)) << 4);
        size_t so = ((size_t)row * SEQ + q) * DK + g * 8;
        cp16(d, g_Qh + so);
        cp16(d + 16384, g_Ql + so);
    }
    CP_COMMIT();

    const float* rq = rel + (size_t)q * SEQ * DK;
    float4 rv[4];
    auto ldgR = [&](int kt) {
        const float* src = rq + (size_t)kt * 64 * DK;
        #pragma unroll
        for (int i = 0; i < 4; i++)
            rv[i] = *(const float4*)(src + (i * 256 + t) * 4);
    };
    auto stsR = [&](int st) {
        char* Rh = basec + 32768 + st * E2_RSTG;
        char* Rl = Rh + 8192;
        #pragma unroll
        for (int i = 0; i < 4; i++) {
            int o = (i * 256 + t) * 4;
            int kr = o >> 6, d = o & 63;
            uint32_t wh0, wl0, wh1, wl1;
            split_pack(rv[i].x, rv[i].y, wh0, wl0);
            split_pack(rv[i].z, rv[i].w, wh1, wl1);
            uint32_t byte = (uint32_t)kr * 128u
                          + (uint32_t)((((d >> 3) ^ (kr & 7))) << 4)
                          + (uint32_t)((d & 7) << 1);
            *(uint2*)(Rh + byte) = make_uint2(wh0, wh1);
            *(uint2*)(Rl + byte) = make_uint2(wl0, wl1);
        }
    };

    ldgR(0);
    stsR(0);
    CP_WAIT0();
    __syncthreads();

    const int wm = wid & 3, wn = wid >> 2;
    const int sub = lid >> 3, rsub = lid & 7;
    const int frow = ((sub & 1) << 3) + rsub;
    const int fkg = sub >> 1;
    const uint32_t sx = (uint32_t)rsub << 4;
    const uint32_t a_off = (uint32_t)(wm * 32 + frow) * 128u;
    const uint32_t b_off = (uint32_t)(wn * 32 + frow) * 128u;
    const int g = lid >> 2, t4 = lid & 3;

    for (int kt = 0; kt < 16; kt++) {
        if (kt + 1 < 16) ldgR(kt + 1);

        float acc[2][4][4];
        #pragma unroll
        for (int i = 0; i < 2; i++)
            #pragma unroll
            for (int j = 0; j < 4; j++)
                #pragma unroll
                for (int k = 0; k < 4; k++) acc[i][j][k] = 0.f;

        uint32_t AhB = Qa + a_off, AlB = AhB + 16384;
        uint32_t S = Ra + (kt & 1) * E2_RSTG;
        uint32_t BhB = S + b_off, BlB = BhB + 8192;
        #pragma unroll
        for (int ks = 0; ks < 4; ks++) {
            uint32_t koff = ((uint32_t)(ks * 32 + fkg * 16)) ^ sx;
            uint32_t ah[2][4], al[2][4], bhf[8], blf[8];
            #pragma unroll
            for (int mt = 0; mt < 2; mt++) {
                ldsm_x4(ah[mt], AhB + mt * 2048 + koff);
                ldsm_x4(al[mt], AlB + mt * 2048 + koff);
            }
            ldsm_x4(bhf + 0, BhB + koff);
            ldsm_x4(bhf + 4, BhB + 2048 + koff);
            ldsm_x4(blf + 0, BlB + koff);
            ldsm_x4(blf + 4, BlB + 2048 + koff);
            #pragma unroll
            for (int mt = 0; mt < 2; mt++)
                #pragma unroll
                for (int nt = 0; nt < 4; nt++) {
                    int cb = (nt >> 1) * 4, od = nt & 1;
                    mma_bf16(acc[mt][nt], ah[mt], bhf[cb + od], bhf[cb + od + 2]);
                    mma_bf16(acc[mt][nt], ah[mt], blf[cb + od], blf[cb + od + 2]);
                    mma_bf16(acc[mt][nt], al[mt], bhf[cb + od], bhf[cb + od + 2]);
                }
        }

        #pragma unroll
        for (int mt = 0; mt < 2; mt++)
            #pragma unroll
            for (int half = 0; half < 2; half++) {
                int bh = wm * 32 + mt * 16 + g + half * 8;
                #pragma unroll
                for (int nt = 0; nt < 4; nt++) {
                    int k = kt * 64 + wn * 32 + nt * 8 + 2 * t4;
                    size_t off = ((size_t)bh * SEQ + q) * SEQ + k;
                    *(float2*)(g_E2 + off) = make_float2(
                        acc[mt][nt][2 * half + 0], acc[mt][nt][2 * half + 1]);
                }
            }

        if (kt + 1 < 16) stsR((kt + 1) & 1);  // other buffer; safe pre-sync
        __syncthreads();
    }
}

// ---------------------------------------------------------------------------
// Fused attention (unchanged, passing). mask is int32 (jax bool -> int32).
// ---------------------------------------------------------------------------
#define ATTN_SMEM_FLOATS (64 * 64 * 3 + 64 * 68)
#define ATTN_SMEM_BYTES  (ATTN_SMEM_FLOATS * 4)

__global__ __launch_bounds__(256, 2)
void attn_kernel(const int* __restrict__ mask, float* __restrict__ out)
{
    extern __shared__ float sm[];
    float* Qst = sm;
    float* Kst = sm + 4096;
    float* Vs  = sm + 8192;
    float* Ssm = sm + 12288;

    const int t  = threadIdx.x;
    const int tx = t & 15, ty = t >> 4;
    const int q0 = blockIdx.x * 64;
    const int bh = blockIdx.y;
    const int b  = bh >> 4, h = bh & 15;

    const float* qg = g_Q + ((size_t)bh * SEQ + q0) * DK;
    #pragma unroll
    for (int p = 0; p < 16; p++) {
        int idx = p * 256 + t;
        int c = idx >> 6, d = idx & 63;
        Qst[(d << 6) + ((((c >> 2) ^ (d & 15)) << 2) | (c & 3))] = qg[idx];
    }

    float m_[4], l_[4], o_[4][4];
    #pragma unroll
    for (int i = 0; i < 4; i++) {
        m_[i] = -1e30f; l_[i] = 0.f;
        #pragma unroll
        for (int j = 0; j < 4; j++) o_[i][j] = 0.f;
    }

    const float* kg  = g_K + (size_t)bh * SEQ * DK;
    const float* vg  = g_V + (size_t)bh * SEQ * DK;
    const float* e2g = g_E2 + ((size_t)bh * SEQ + q0) * SEQ;
    const int*   mg  = mask + ((size_t)b * SEQ + q0) * SEQ;

    for (int kt = 0; kt < SEQ; kt += 64) {
        __syncthreads();
        const float* kgt = kg + (size_t)kt * DK;
        #pragma unroll
        for (int p = 0; p < 16; p++) {
            int idx = p * 256 + t;
            int c = idx >> 6, d = idx & 63;
            Kst[(d << 6) + ((((c >> 2) ^ (d & 15)) << 2) | (c & 3))] = kgt[idx];
        }
        const float* vgt = vg + (size_t)kt * DK;
        #pragma unroll
        for (int p = 0; p < 4; p++) {
            int idx = (p * 256 + t) << 2;
            *(float4*)&Vs[idx] = *(const float4*)&vgt[idx];
        }
        __syncthreads();

        float4 e2v[4];
        int4   mk[4];
        #pragma unroll
        for (int i = 0; i < 4; i++) {
            int r = (ty << 2) + i;
            e2v[i] = *(const float4*)&e2g[(size_t)r * SEQ + kt + (tx << 2)];
            mk[i]  = *(const int4*)&mg[(size_t)r * SEQ + kt + (tx << 2)];
        }

        float s_[4][4] = {};
        #pragma unroll 16
        for (int d = 0; d < 64; d++) {
            int sw = d & 15;
            float4 qv = *(const float4*)&Qst[(d << 6) + ((ty ^ sw) << 2)];
            float4 kv = *(const float4*)&Kst[(d << 6) + ((tx ^ sw) << 2)];
            float qa[4] = {qv.x, qv.y, qv.z, qv.w};
            float ka[4] = {kv.x, kv.y, kv.z, kv.w};
            #pragma unroll
            for (int i = 0; i < 4; i++)
                #pragma unroll
                for (int j = 0; j < 4; j++)
                    s_[i][j] += qa[i] * ka[j];
        }

        #pragma unroll
        for (int i = 0; i < 4; i++) {
            float e[4] = {e2v[i].x, e2v[i].y, e2v[i].z, e2v[i].w};
            int   mm[4] = {mk[i].x, mk[i].y, mk[i].z, mk[i].w};
            #pragma unroll
            for (int j = 0; j < 4; j++) {
                float v = s_[i][j] * 0.125f + e[j];
                s_[i][j] = mm[j] ? -1e8f : v;
            }
        }

        #pragma unroll
        for (int i = 0; i < 4; i++) {
            float tm = fmaxf(fmaxf(s_[i][0], s_[i][1]), fmaxf(s_[i][2], s_[i][3]));
            #pragma unroll
            for (int w = 8; w >= 1; w >>= 1)
                tm = fmaxf(tm, __shfl_xor_sync(0xffffffffu, tm, w));
            float mn = fmaxf(m_[i], tm);
            float sc = __expf(m_[i] - mn);
            m_[i] = mn;
            float ts = 0.f;
            #pragma unroll
            for (int j = 0; j < 4; j++) {
                float p = __expf(s_[i][j] - mn);
                s_[i][j] = p;
                ts += p;
            }
            #pragma unroll
            for (int w = 8; w >= 1; w >>= 1)
                ts += __shfl_xor_sync(0xffffffffu, ts, w);
            l_[i] = l_[i] * sc + ts;
            #pragma unroll
            for (int j = 0; j < 4; j++) o_[i][j] *= sc;
            *(float4*)&Ssm[((ty << 2) + i) * 68 + (tx << 2)] =
                make_float4(s_[i][0], s_[i][1], s_[i][2], s_[i][3]);
        }
        __syncthreads();

        #pragma unroll 16
        for (int k = 0; k < 64; k++) {
            float4 vv = *(const float4*)&Vs[(k << 6) + (tx << 2)];
            float va[4] = {vv.x, vv.y, vv.z, vv.w};
            #pragma unroll
            for (int i = 0; i < 4; i++) {
                float p = Ssm[((ty << 2) + i) * 68 + k];
                #pragma unroll
                for (int j = 0; j < 4; j++)
                    o_[i][j] += p * va[j];
            }
        }
    }

    #pragma unroll
    for (int i = 0; i < 4; i++) {
        float inv = 1.0f / l_[i];
        int q = q0 + (ty << 2) + i;
        float4 ov = make_float4(o_[i][0] * inv, o_[i][1] * inv,
                                o_[i][2] * inv, o_[i][3] * inv);
        *(float4*)&out[((size_t)b * SEQ + q) * DMOD + h * DK + (tx << 2)] = ov;
    }
}

// ---------------------------------------------------------------------------
extern "C" void kernel_launch(void* const* d_in, const int* in_sizes, int n_in,
                              void* d_out, int out_size)
{
    const float* query = (const float*)d_in[0];
    const float* key   = (const float*)d_in[1];
    const float* value = (const float*)d_in[2];
    const float* rel   = (const float*)d_in[3];
    const float* W_q   = (const float*)d_in[4];
    const float* b_q   = (const float*)d_in[5];
    const float* W_k   = (const float*)d_in[6];
    const float* b_k   = (const float*)d_in[7];
    const float* W_v   = (const float*)d_in[8];
    const float* b_v   = (const float*)d_in[9];
    const int*   mask  = (const int*)d_in[10];
    float* out = (float*)d_out;

    cudaFuncSetAttribute(proj_tc_kernel,
                         cudaFuncAttributeMaxDynamicSharedMemorySize, PROJ_SMEM);
    cudaFuncSetAttribute(e2_tc_kernel,
                         cudaFuncAttributeMaxDynamicSharedMemorySize, E2_SMEM);
    cudaFuncSetAttribute(attn_kernel,
                         cudaFuncAttributeMaxDynamicSharedMemorySize, ATTN_SMEM_BYTES);

    conv_x_kernel<<<dim3(8192, 3), 256>>>(query, key, value);
    conv_w_kernel<<<dim3(32, 32, 3), 256>>>(W_q, W_k, W_v);

    proj_tc_kernel<<<dim3(DMOD / 64, (BB * SEQ) / 128, 3), 256, PROJ_SMEM>>>(
        b_q, b_k, b_v);

    e2_tc_kernel<<<SEQ, 256, E2_SMEM>>>(rel);

    attn_kernel<<<dim3(SEQ / 64, NBH), 256, ATTN_SMEM_BYTES>>>(mask, out);
}

// round 6
// speedup vs baseline: 2.9714x; 1.7621x over previous
#include <cuda_runtime.h>
#include <cuda_bf16.h>
#include <cuda_fp16.h>
#include <cstdint>

#define BB   8
#define SEQ  1024
#define DMOD 1024
#define NH   16
#define DK   64
#define NBH  128   // BB*NH

// Scratch (device globals — allocation-free per harness rules)
__device__ __nv_bfloat16 g_Xh[3ull * 8192 * 1024];
__device__ __nv_bfloat16 g_Xl[3ull * 8192 * 1024];
__device__ __nv_bfloat16 g_Wth[3ull * 1024 * 1024];
__device__ __nv_bfloat16 g_Wtl[3ull * 1024 * 1024];
__device__ __nv_bfloat16 g_Qh[(size_t)NBH * SEQ * DK];
__device__ __nv_bfloat16 g_Ql[(size_t)NBH * SEQ * DK];
__device__ __nv_bfloat16 g_Kh[(size_t)NBH * SEQ * DK];
__device__ __nv_bfloat16 g_Kl[(size_t)NBH * SEQ * DK];
__device__ __nv_bfloat16 g_Vh[(size_t)NBH * SEQ * DK];
__device__ __nv_bfloat16 g_Vl[(size_t)NBH * SEQ * DK];
__device__ __half        g_E2h[(size_t)NBH * SEQ * SEQ];  // masked E2, fp16

// ---------------------------------------------------------------------------
// Helpers
// ---------------------------------------------------------------------------
__device__ __forceinline__ uint32_t smem_u32(const void* p) {
    uint32_t a;
    asm("{ .reg .u64 t; cvta.to.shared.u64 t, %1; cvt.u32.u64 %0, t; }"
        : "=r"(a) : "l"(p));
    return a;
}
__device__ __forceinline__ void ldsm_x4(uint32_t* r, uint32_t addr) {
    asm volatile("ldmatrix.sync.aligned.m8n8.x4.shared.b16 {%0,%1,%2,%3}, [%4];"
                 : "=r"(r[0]), "=r"(r[1]), "=r"(r[2]), "=r"(r[3]) : "r"(addr));
}
__device__ __forceinline__ void ldsm_x4_t(uint32_t* r, uint32_t addr) {
    asm volatile("ldmatrix.sync.aligned.m8n8.x4.trans.shared.b16 {%0,%1,%2,%3}, [%4];"
                 : "=r"(r[0]), "=r"(r[1]), "=r"(r[2]), "=r"(r[3]) : "r"(addr));
}
__device__ __forceinline__ void mma_bf16(float* d, const uint32_t* a,
                                         uint32_t b0, uint32_t b1) {
    asm volatile(
        "mma.sync.aligned.m16n8k16.row.col.f32.bf16.bf16.f32 "
        "{%0,%1,%2,%3}, {%4,%5,%6,%7}, {%8,%9}, {%0,%1,%2,%3};"
        : "+f"(d[0]), "+f"(d[1]), "+f"(d[2]), "+f"(d[3])
        : "r"(a[0]), "r"(a[1]), "r"(a[2]), "r"(a[3]), "r"(b0), "r"(b1));
}
__device__ __forceinline__ void split_pack(float x0, float x1,
                                           uint32_t& wh, uint32_t& wl) {
    __nv_bfloat16 h0 = __float2bfloat16_rn(x0);
    __nv_bfloat16 h1 = __float2bfloat16_rn(x1);
    __nv_bfloat16 l0 = __float2bfloat16_rn(x0 - __bfloat162float(h0));
    __nv_bfloat16 l1 = __float2bfloat16_rn(x1 - __bfloat162float(h1));
    wh = (uint32_t)*(unsigned short*)&h0 | ((uint32_t)*(unsigned short*)&h1 << 16);
    wl = (uint32_t)*(unsigned short*)&l0 | ((uint32_t)*(unsigned short*)&l1 << 16);
}
__device__ __forceinline__ void cp16(uint32_t dst, const void* src) {
    asm volatile("cp.async.cg.shared.global [%0], [%1], 16;"
                 :: "r"(dst), "l"(src));
}
#define CP_COMMIT() asm volatile("cp.async.commit_group;" ::: "memory")
#define CP_WAIT1()  asm volatile("cp.async.wait_group 1;" ::: "memory")
#define CP_WAIT0()  asm volatile("cp.async.wait_group 0;" ::: "memory")

// ---------------------------------------------------------------------------
// Pre-conversion kernels
// ---------------------------------------------------------------------------
__global__ __launch_bounds__(256)
void conv_x_kernel(const float* __restrict__ xq, const float* __restrict__ xk,
                   const float* __restrict__ xv)
{
    const int pz = blockIdx.y;
    const float* X = (pz == 0) ? xq : (pz == 1) ? xk : xv;
    size_t i4 = ((size_t)blockIdx.x * 256 + threadIdx.x) * 4;
    float4 v = *(const float4*)(X + i4);
    uint32_t h0, l0, h1, l1;
    split_pack(v.x, v.y, h0, l0);
    split_pack(v.z, v.w, h1, l1);
    size_t base = (size_t)pz * (8192ull * 1024) + i4;
    *(uint2*)&g_Xh[base] = make_uint2(h0, h1);
    *(uint2*)&g_Xl[base] = make_uint2(l0, l1);
}

__global__ __launch_bounds__(256)
void conv_w_kernel(const float* __restrict__ wq, const float* __restrict__ wk,
                   const float* __restrict__ wv)
{
    __shared__ float sm[32][33];
    const int pz = blockIdx.z;
    const float* W = (pz == 0) ? wq : (pz == 1) ? wk : wv;
    const int n0 = blockIdx.x * 32, k0 = blockIdx.y * 32;
    const int t = threadIdx.x, r = t >> 5, c = t & 31;
    #pragma unroll
    for (int i = 0; i < 4; i++)
        sm[r + i * 8][c] = W[(size_t)(k0 + r + i * 8) * DMOD + n0 + c];
    __syncthreads();
    size_t base = (size_t)pz * (1024ull * 1024);
    #pragma unroll
    for (int i = 0; i < 4; i++) {
        int n = r + i * 8;
        float x = sm[c][n];
        __nv_bfloat16 h = __float2bfloat16_rn(x);
        __nv_bfloat16 l = __float2bfloat16_rn(x - __bfloat162float(h));
        g_Wth[base + (size_t)(n0 + n) * DMOD + k0 + c] = h;
        g_Wtl[base + (size_t)(n0 + n) * DMOD + k0 + c] = l;
    }
}

// ---------------------------------------------------------------------------
// Projection GEMM (bf16x3, cp.async). Outputs bf16 hi/lo head-split Q/K/V.
// ---------------------------------------------------------------------------
#define PROJ_STAGE 49152
#define PROJ_SMEM  (2 * PROJ_STAGE + 1024)
#define NCHUNK     16

__global__ __launch_bounds__(256, 2)
void proj_tc_kernel(const float* __restrict__ bq, const float* __restrict__ bk,
                    const float* __restrict__ bv)
{
    extern __shared__ char dsm[];
    __shared__ float sbias[64];

    const int t = threadIdx.x, wid = t >> 5, lid = t & 31;
    const int n0 = blockIdx.x * 64;
    const int m0 = blockIdx.y * 128;
    const int pz = blockIdx.z;

    const float* bias = (pz == 0) ? bq : (pz == 1) ? bk : bv;
    __nv_bfloat16* outh = (pz == 0) ? g_Qh : (pz == 1) ? g_Kh : g_Vh;
    __nv_bfloat16* outl = (pz == 0) ? g_Ql : (pz == 1) ? g_Kl : g_Vl;
    const __nv_bfloat16* Xh = g_Xh + (size_t)pz * (8192ull * 1024);
    const __nv_bfloat16* Xl = g_Xl + (size_t)pz * (8192ull * 1024);
    const __nv_bfloat16* Wh = g_Wth + (size_t)pz * (1024ull * 1024);
    const __nv_bfloat16* Wl = g_Wtl + (size_t)pz * (1024ull * 1024);

    uint32_t raw = smem_u32(dsm);
    uint32_t base_a = raw + ((1024u - (raw & 1023u)) & 1023u);

    if (t < 64) sbias[t] = bias[n0 + t];

    auto issue = [&](int c, int st) {
        uint32_t S = base_a + st * PROJ_STAGE;
        #pragma unroll
        for (int i = 0; i < 4; i++) {
            int idx = i * 256 + t, row = idx >> 3, g = idx & 7;
            uint32_t d = S + row * 128 + (uint32_t)((g ^ (row & 7)) << 4);
            size_t so = (size_t)(m0 + row) * DMOD + c * 64 + g * 8;
            cp16(d, Xh + so);
            cp16(d + 16384, Xl + so);
        }
        #pragma unroll
        for (int i = 0; i < 2; i++) {
            int idx = i * 256 + t, row = idx >> 3, g = idx & 7;
            uint32_t d = S + 32768 + row * 128 + (uint32_t)((g ^ (row & 7)) << 4);
            size_t so = (size_t)(n0 + row) * DMOD + c * 64 + g * 8;
            cp16(d, Wh + so);
            cp16(d + 8192, Wl + so);
        }
        CP_COMMIT();
    };

    const int wm = wid & 3, wn = wid >> 2;
    const int sub = lid >> 3, rsub = lid & 7;
    const int frow = ((sub & 1) << 3) + rsub;
    const int fkg = sub >> 1;
    const uint32_t sx = (uint32_t)rsub << 4;
    const uint32_t a_off = (uint32_t)(wm * 32 + frow) * 128u;
    const uint32_t b_off = (uint32_t)(wn * 32 + frow) * 128u;

    float acc[2][4][4];
    #pragma unroll
    for (int i = 0; i < 2; i++)
        #pragma unroll
        for (int j = 0; j < 4; j++)
            #pragma unroll
            for (int k = 0; k < 4; k++) acc[i][j][k] = 0.f;

    auto mma_stage = [&](int st) {
        uint32_t S = base_a + st * PROJ_STAGE;
        uint32_t AhB = S + a_off, AlB = AhB + 16384;
        uint32_t BhB = S + 32768 + b_off, BlB = BhB + 8192;
        #pragma unroll
        for (int ks = 0; ks < 4; ks++) {
            uint32_t koff = ((uint32_t)(ks * 32 + fkg * 16)) ^ sx;
            uint32_t ah[2][4], al[2][4], bhf[8], blf[8];
            #pragma unroll
            for (int mt = 0; mt < 2; mt++) {
                ldsm_x4(ah[mt], AhB + mt * 2048 + koff);
                ldsm_x4(al[mt], AlB + mt * 2048 + koff);
            }
            ldsm_x4(bhf + 0, BhB + koff);
            ldsm_x4(bhf + 4, BhB + 2048 + koff);
            ldsm_x4(blf + 0, BlB + koff);
            ldsm_x4(blf + 4, BlB + 2048 + koff);
            #pragma unroll
            for (int mt = 0; mt < 2; mt++)
                #pragma unroll
                for (int nt = 0; nt < 4; nt++) {
                    int cb = (nt >> 1) * 4, od = nt & 1;
                    mma_bf16(acc[mt][nt], ah[mt], bhf[cb + od], bhf[cb + od + 2]);
                    mma_bf16(acc[mt][nt], ah[mt], blf[cb + od], blf[cb + od + 2]);
                    mma_bf16(acc[mt][nt], al[mt], bhf[cb + od], bhf[cb + od + 2]);
                }
        }
    };

    issue(0, 0);
    issue(1, 1);
    for (int c = 0; c < NCHUNK; c++) {
        if (c < NCHUNK - 1) CP_WAIT1(); else CP_WAIT0();
        __syncthreads();
        mma_stage(c & 1);
        if (c + 2 < NCHUNK) {
            __syncthreads();
            issue(c + 2, c & 1);
        }
    }

    const int g = lid >> 2, t4 = lid & 3;
    const int h = blockIdx.x;
    #pragma unroll
    for (int mt = 0; mt < 2; mt++)
        #pragma unroll
        for (int half = 0; half < 2; half++) {
            int m = m0 + wm * 32 + mt * 16 + g + half * 8;
            int b = m >> 10, s = m & (SEQ - 1);
            #pragma unroll
            for (int nt = 0; nt < 4; nt++) {
                int d = wn * 32 + nt * 8 + 2 * t4;
                size_t off = (((size_t)(b * NH + h)) * SEQ + s) * DK + d;
                float vx = acc[mt][nt][2 * half + 0] + sbias[d];
                float vy = acc[mt][nt][2 * half + 1] + sbias[d + 1];
                uint32_t wh, wl;
                split_pack(vx, vy, wh, wl);
                *(uint32_t*)&outh[off] = wh;
                *(uint32_t*)&outl[off] = wl;
            }
        }
}

// ---------------------------------------------------------------------------
// E2 (bf16x3 mma): per block one q. Output fp16 with mask folded (-30000).
// ---------------------------------------------------------------------------
#define E2_RSTG  16384
#define E2_SMEM  (32768 + 2 * E2_RSTG + 1024)

__global__ __launch_bounds__(256, 2)
void e2_tc_kernel(const float* __restrict__ rel, const int* __restrict__ maskp)
{
    extern __shared__ char dsm[];
    const int t = threadIdx.x, wid = t >> 5, lid = t & 31;
    const int q = blockIdx.x;

    uint32_t raw = smem_u32(dsm);
    uint32_t base_a = raw + ((1024u - (raw & 1023u)) & 1023u);
    char* basec = dsm + (base_a - raw);
    uint32_t Qa = base_a;
    uint32_t Ra = base_a + 32768;

    #pragma unroll
    for (int i = 0; i < 4; i++) {
        int idx = i * 256 + t, row = idx >> 3, g = idx & 7;
        uint32_t d = Qa + row * 128 + (uint32_t)((g ^ (row & 7)) << 4);
        size_t so = ((size_t)row * SEQ + q) * DK + g * 8;
        cp16(d, g_Qh + so);
        cp16(d + 16384, g_Ql + so);
    }
    CP_COMMIT();

    const float* rq = rel + (size_t)q * SEQ * DK;
    float4 rv[4];
    auto ldgR = [&](int kt) {
        const float* src = rq + (size_t)kt * 64 * DK;
        #pragma unroll
        for (int i = 0; i < 4; i++)
            rv[i] = *(const float4*)(src + (i * 256 + t) * 4);
    };
    auto stsR = [&](int st) {
        char* Rh = basec + 32768 + st * E2_RSTG;
        char* Rl = Rh + 8192;
        #pragma unroll
        for (int i = 0; i < 4; i++) {
            int o = (i * 256 + t) * 4;
            int kr = o >> 6, d = o & 63;
            uint32_t wh0, wl0, wh1, wl1;
            split_pack(rv[i].x, rv[i].y, wh0, wl0);
            split_pack(rv[i].z, rv[i].w, wh1, wl1);
            uint32_t byte = (uint32_t)kr * 128u
                          + (uint32_t)((((d >> 3) ^ (kr & 7))) << 4)
                          + (uint32_t)((d & 7) << 1);
            *(uint2*)(Rh + byte) = make_uint2(wh0, wh1);
            *(uint2*)(Rl + byte) = make_uint2(wl0, wl1);
        }
    };

    ldgR(0);
    stsR(0);
    CP_WAIT0();
    __syncthreads();

    const int wm = wid & 3, wn = wid >> 2;
    const int sub = lid >> 3, rsub = lid & 7;
    const int frow = ((sub & 1) << 3) + rsub;
    const int fkg = sub >> 1;
    const uint32_t sx = (uint32_t)rsub << 4;
    const uint32_t a_off = (uint32_t)(wm * 32 + frow) * 128u;
    const uint32_t b_off = (uint32_t)(wn * 32 + frow) * 128u;
    const int g = lid >> 2, t4 = lid & 3;

    for (int kt = 0; kt < 16; kt++) {
        if (kt + 1 < 16) ldgR(kt + 1);

        float acc[2][4][4];
        #pragma unroll
        for (int i = 0; i < 2; i++)
            #pragma unroll
            for (int j = 0; j < 4; j++)
                #pragma unroll
                for (int k = 0; k < 4; k++) acc[i][j][k] = 0.f;

        uint32_t AhB = Qa + a_off, AlB = AhB + 16384;
        uint32_t S = Ra + (kt & 1) * E2_RSTG;
        uint32_t BhB = S + b_off, BlB = BhB + 8192;
        #pragma unroll
        for (int ks = 0; ks < 4; ks++) {
            uint32_t koff = ((uint32_t)(ks * 32 + fkg * 16)) ^ sx;
            uint32_t ah[2][4], al[2][4], bhf[8], blf[8];
            #pragma unroll
            for (int mt = 0; mt < 2; mt++) {
                ldsm_x4(ah[mt], AhB + mt * 2048 + koff);
                ldsm_x4(al[mt], AlB + mt * 2048 + koff);
            }
            ldsm_x4(bhf + 0, BhB + koff);
            ldsm_x4(bhf + 4, BhB + 2048 + koff);
            ldsm_x4(blf + 0, BlB + koff);
            ldsm_x4(blf + 4, BlB + 2048 + koff);
            #pragma unroll
            for (int mt = 0; mt < 2; mt++)
                #pragma unroll
                for (int nt = 0; nt < 4; nt++) {
                    int cb = (nt >> 1) * 4, od = nt & 1;
                    mma_bf16(acc[mt][nt], ah[mt], bhf[cb + od], bhf[cb + od + 2]);
                    mma_bf16(acc[mt][nt], ah[mt], blf[cb + od], blf[cb + od + 2]);
                    mma_bf16(acc[mt][nt], al[mt], bhf[cb + od], bhf[cb + od + 2]);
                }
        }

        #pragma unroll
        for (int mt = 0; mt < 2; mt++)
            #pragma unroll
            for (int half = 0; half < 2; half++) {
                int bh = wm * 32 + mt * 16 + g + half * 8;
                int b = bh >> 4;
                #pragma unroll
                for (int nt = 0; nt < 4; nt++) {
                    int k = kt * 64 + wn * 32 + nt * 8 + 2 * t4;
                    int2 mk = *(const int2*)&maskp[((size_t)b * SEQ + q) * SEQ + k];
                    float v0 = mk.x ? -30000.f : acc[mt][nt][2 * half + 0];
                    float v1 = mk.y ? -30000.f : acc[mt][nt][2 * half + 1];
                    *(__half2*)&g_E2h[((size_t)bh * SEQ + q) * SEQ + k] =
                        __floats2half2_rn(v0, v1);
                }
            }

        if (kt + 1 < 16) stsR((kt + 1) & 1);
        __syncthreads();
    }
}

// ---------------------------------------------------------------------------
// Attention via mma.sync bf16x3. CTA = 128 q-rows x bh; 8 warps m16 x n64.
// ---------------------------------------------------------------------------
#define ATTN_SMEM (98304 + 1024)

__global__ __launch_bounds__(256, 2)
void attn_tc_kernel(float* __restrict__ out)
{
    extern __shared__ char dsm[];
    const int t = threadIdx.x, wq = t >> 5, lid = t & 31;
    const int q0 = blockIdx.x * 128;
    const int bh = blockIdx.y, b = bh >> 4, h = bh & 15;
    const int g = lid >> 2, t4 = lid & 3;

    uint32_t raw = smem_u32(dsm);
    uint32_t base_a = raw + ((1024u - (raw & 1023u)) & 1023u);
    const uint32_t Qa = base_a;            // Qh 16K | Ql 16K
    const uint32_t KVa = base_a + 32768;   // per stage: Kh|Kl|Vh|Vl 8K each

    #pragma unroll
    for (int i = 0; i < 4; i++) {
        int idx = i * 256 + t, row = idx >> 3, gg = idx & 7;
        uint32_t d = Qa + row * 128 + (uint32_t)((gg ^ (row & 7)) << 4);
        size_t so = ((size_t)bh * SEQ + q0 + row) * DK + gg * 8;
        cp16(d, g_Qh + so);
        cp16(d + 16384, g_Ql + so);
    }
    auto issueKV = [&](int kt, int st) {
        uint32_t S = KVa + st * 32768;
        #pragma unroll
        for (int i = 0; i < 2; i++) {
            int idx = i * 256 + t, row = idx >> 3, gg = idx & 7;
            uint32_t d = S + row * 128 + (uint32_t)((gg ^ (row & 7)) << 4);
            size_t so = ((size_t)bh * SEQ + kt + row) * DK + gg * 8;
            cp16(d, g_Kh + so);
            cp16(d + 8192, g_Kl + so);
            cp16(d + 16384, g_Vh + so);
            cp16(d + 24576, g_Vl + so);
        }
        CP_COMMIT();
    };
    issueKV(0, 0);     // group0 = Q + KV0
    issueKV(64, 1);    // group1 = KV1

    float o[8][4];
    #pragma unroll
    for (int i = 0; i < 8; i++)
        #pragma unroll
        for (int j = 0; j < 4; j++) o[i][j] = 0.f;
    float m0 = -1e30f, m1 = -1e30f, l0 = 0.f, l1 = 0.f;

    const int arow = wq * 16 + ((lid >> 3) & 1) * 8 + (lid & 7);
    const __half* e2base =
        g_E2h + ((size_t)bh * SEQ + q0 + wq * 16 + g) * SEQ + 2 * t4;

    for (int it = 0; it < 16; it++) {
        if (it < 15) CP_WAIT1(); else CP_WAIT0();
        __syncthreads();
        const int kt = it * 64;
        const uint32_t S = KVa + (it & 1) * 32768;

        // prefetch E2 (overlaps QK mma)
        __half2 e2a[8], e2b[8];
        #pragma unroll
        for (int nt = 0; nt < 8; nt++) {
            e2a[nt] = *(const __half2*)(e2base + kt + nt * 8);
            e2b[nt] = *(const __half2*)(e2base + 8 * SEQ + kt + nt * 8);
        }

        float s[8][4];
        #pragma unroll
        for (int i = 0; i < 8; i++)
            #pragma unroll
            for (int j = 0; j < 4; j++) s[i][j] = 0.f;

        #pragma unroll
        for (int j = 0; j < 4; j++) {
            uint32_t qh[4], ql[4];
            int agrp = j * 2 + (lid >> 4);
            uint32_t qaddr = Qa + arow * 128 + (uint32_t)((agrp ^ (arow & 7)) << 4);
            ldsm_x4(qh, qaddr);
            ldsm_x4(ql, qaddr + 16384);
            #pragma unroll
            for (int p = 0; p < 4; p++) {
                uint32_t kh[4], kl[4];
                int krow = p * 16 + (lid >> 4) * 8 + (lid & 7);
                int kgrp = j * 2 + ((lid >> 3) & 1);
                uint32_t kaddr = S + krow * 128 + (uint32_t)((kgrp ^ (krow & 7)) << 4);
                ldsm_x4(kh, kaddr);
                ldsm_x4(kl, kaddr + 8192);
                mma_bf16(s[2 * p],     qh, kh[0], kh[1]);
                mma_bf16(s[2 * p],     qh, kl[0], kl[1]);
                mma_bf16(s[2 * p],     ql, kh[0], kh[1]);
                mma_bf16(s[2 * p + 1], qh, kh[2], kh[3]);
                mma_bf16(s[2 * p + 1], qh, kl[2], kl[3]);
                mma_bf16(s[2 * p + 1], ql, kh[2], kh[3]);
            }
        }

        // scale + E2 (mask folded in), softmax
        #pragma unroll
        for (int nt = 0; nt < 8; nt++) {
            float2 f0 = __half22float2(e2a[nt]);
            float2 f1 = __half22float2(e2b[nt]);
            s[nt][0] = fmaf(s[nt][0], 0.125f, f0.x);
            s[nt][1] = fmaf(s[nt][1], 0.125f, f0.y);
            s[nt][2] = fmaf(s[nt][2], 0.125f, f1.x);
            s[nt][3] = fmaf(s[nt][3], 0.125f, f1.y);
        }
        float mx0 = -1e30f, mx1 = -1e30f;
        #pragma unroll
        for (int nt = 0; nt < 8; nt++) {
            mx0 = fmaxf(mx0, fmaxf(s[nt][0], s[nt][1]));
            mx1 = fmaxf(mx1, fmaxf(s[nt][2], s[nt][3]));
        }
        #pragma unroll
        for (int w = 1; w <= 2; w <<= 1) {
            mx0 = fmaxf(mx0, __shfl_xor_sync(0xffffffffu, mx0, w));
            mx1 = fmaxf(mx1, __shfl_xor_sync(0xffffffffu, mx1, w));
        }
        float mn0 = fmaxf(m0, mx0), mn1 = fmaxf(m1, mx1);
        float sc0 = __expf(m0 - mn0), sc1 = __expf(m1 - mn1);
        m0 = mn0; m1 = mn1;
        float sum0 = 0.f, sum1 = 0.f;
        #pragma unroll
        for (int nt = 0; nt < 8; nt++) {
            s[nt][0] = __expf(s[nt][0] - mn0); sum0 += s[nt][0];
            s[nt][1] = __expf(s[nt][1] - mn0); sum0 += s[nt][1];
            s[nt][2] = __expf(s[nt][2] - mn1); sum1 += s[nt][2];
            s[nt][3] = __expf(s[nt][3] - mn1); sum1 += s[nt][3];
        }
        #pragma unroll
        for (int w = 1; w <= 2; w <<= 1) {
            sum0 += __shfl_xor_sync(0xffffffffu, sum0, w);
            sum1 += __shfl_xor_sync(0xffffffffu, sum1, w);
        }
        l0 = l0 * sc0 + sum0;
        l1 = l1 * sc1 + sum1;
        #pragma unroll
        for (int nt = 0; nt < 8; nt++) {
            o[nt][0] *= sc0; o[nt][1] *= sc0;
            o[nt][2] *= sc1; o[nt][3] *= sc1;
        }

        // P @ V
        #pragma unroll
        for (int j = 0; j < 4; j++) {
            uint32_t ph[4], pl[4];
            split_pack(s[2 * j][0],     s[2 * j][1],     ph[0], pl[0]);
            split_pack(s[2 * j][2],     s[2 * j][3],     ph[1], pl[1]);
            split_pack(s[2 * j + 1][0], s[2 * j + 1][1], ph[2], pl[2]);
            split_pack(s[2 * j + 1][2], s[2 * j + 1][3], ph[3], pl[3]);
            #pragma unroll
            for (int pd = 0; pd < 4; pd++) {
                uint32_t vh[4], vl[4];
                int vrow = j * 16 + ((lid >> 3) & 1) * 8 + (lid & 7);
                int vgrp = pd * 2 + (lid >> 4);
                uint32_t vaddr = S + 16384 + vrow * 128
                               + (uint32_t)((vgrp ^ (vrow & 7)) << 4);
                ldsm_x4_t(vh, vaddr);
                ldsm_x4_t(vl, vaddr + 8192);
                mma_bf16(o[2 * pd],     ph, vh[0], vh[1]);
                mma_bf16(o[2 * pd],     ph, vl[0], vl[1]);
                mma_bf16(o[2 * pd],     pl, vh[0], vh[1]);
                mma_bf16(o[2 * pd + 1], ph, vh[2], vh[3]);
                mma_bf16(o[2 * pd + 1], ph, vl[2], vl[3]);
                mma_bf16(o[2 * pd + 1], pl, vh[2], vh[3]);
            }
        }

        __syncthreads();
        if (it + 2 < 16) issueKV((it + 2) * 64, it & 1);
    }

    float inv0 = 1.f / l0, inv1 = 1.f / l1;
    int row0 = q0 + wq * 16 + g;
    #pragma unroll
    for (int nt = 0; nt < 8; nt++) {
        int d = nt * 8 + 2 * t4;
        *(float2*)&out[((size_t)b * SEQ + row0) * DMOD + h * DK + d] =
            make_float2(o[nt][0] * inv0, o[nt][1] * inv0);
        *(float2*)&out[((size_t)b * SEQ + row0 + 8) * DMOD + h * DK + d] =
            make_float2(o[nt][2] * inv1, o[nt][3] * inv1);
    }
}

// ---------------------------------------------------------------------------
extern "C" void kernel_launch(void* const* d_in, const int* in_sizes, int n_in,
                              void* d_out, int out_size)
{
    const float* query = (const float*)d_in[0];
    const float* key   = (const float*)d_in[1];
    const float* value = (const float*)d_in[2];
    const float* rel   = (const float*)d_in[3];
    const float* W_q   = (const float*)d_in[4];
    const float* b_q   = (const float*)d_in[5];
    const float* W_k   = (const float*)d_in[6];
    const float* b_k   = (const float*)d_in[7];
    const float* W_v   = (const float*)d_in[8];
    const float* b_v   = (const float*)d_in[9];
    const int*   mask  = (const int*)d_in[10];
    float* out = (float*)d_out;

    cudaFuncSetAttribute(proj_tc_kernel,
                         cudaFuncAttributeMaxDynamicSharedMemorySize, PROJ_SMEM);
    cudaFuncSetAttribute(e2_tc_kernel,
                         cudaFuncAttributeMaxDynamicSharedMemorySize, E2_SMEM);
    cudaFuncSetAttribute(attn_tc_kernel,
                         cudaFuncAttributeMaxDynamicSharedMemorySize, ATTN_SMEM);

    conv_x_kernel<<<dim3(8192, 3), 256>>>(query, key, value);
    conv_w_kernel<<<dim3(32, 32, 3), 256>>>(W_q, W_k, W_v);

    proj_tc_kernel<<<dim3(DMOD / 64, (BB * SEQ) / 128, 3), 256, PROJ_SMEM>>>(
        b_q, b_k, b_v);

    e2_tc_kernel<<<SEQ, 256, E2_SMEM>>>(rel, mask);

    attn_tc_kernel<<<dim3(SEQ / 128, NBH), 256, ATTN_SMEM>>>(out);
}